// round 15
// baseline (speedup 1.0000x reference)
#include <cuda_runtime.h>
#include <cuda_fp16.h>
#include <math.h>
#include <stdint.h>

#define BATCH   2
#define SEQ     2048
#define DIM     1024
#define NHEAD   16
#define DHEAD   64
#define NLAYER  8
#define DFFN    4096
#define WIN     1024
#define MROWS   (BATCH*SEQ)   // 4096
#define SPLIT_S 128.f
#define SPLIT_INV 0.0078125f   // 1/128
#define NSM     148

// ---------------- scratch (device globals; no allocations) ----------------
__device__ float g_res[MROWS*DIM];
__device__ float g_qkv[MROWS*3*DIM];
__device__ float g_a  [MROWS*DIM];
__device__ float g_x  [MROWS*DIM];

__device__ __half g_hnH [MROWS*DIM];
__device__ __half g_hnM [MROWS*DIM];
__device__ __half g_cxH [MROWS*DIM];
__device__ __half g_cxM [MROWS*DIM];
__device__ __half g_uH  [MROWS*DFFN];
__device__ __half g_uM  [MROWS*DFFN];

// head-major f16 splits for attention
#define AHE (BATCH*NHEAD*SEQ*DHEAD)
__device__ __half g_Qh[AHE];
__device__ __half g_Qm[AHE];
__device__ __half g_Kh[AHE];
__device__ __half g_Km[AHE];
__device__ __half g_Vh[AHE];
__device__ __half g_Vm[AHE];

__device__ __half g_qkvH[NLAYER*3*DIM*DIM];
__device__ __half g_qkvM[NLAYER*3*DIM*DIM];
__device__ __half g_woH [NLAYER*DIM*DIM];
__device__ __half g_woM [NLAYER*DIM*DIM];
__device__ __half g_f1H [NLAYER*2*DFFN*DIM];   // interleaved rows
__device__ __half g_f1M [NLAYER*2*DFFN*DIM];
__device__ __half g_f2H [NLAYER*DIM*DFFN];
__device__ __half g_f2M [NLAYER*DIM*DFFN];

// ---------------- PTX helpers ----------------
__device__ __forceinline__ uint32_t smem_u32(const void* p) {
    uint32_t a;
    asm("{ .reg .u64 t; cvta.to.shared.u64 t, %1; cvt.u32.u64 %0, t; }"
        : "=r"(a) : "l"(p));
    return a;
}
__device__ __forceinline__ void cp16(uint32_t dst, const void* src) {
    asm volatile("cp.async.cg.shared.global [%0], [%1], 16;"
                 :: "r"(dst), "l"(src) : "memory");
}
__device__ __forceinline__ void cp_commit() {
    asm volatile("cp.async.commit_group;" ::: "memory");
}
__device__ __forceinline__ void cp_wait1() {
    asm volatile("cp.async.wait_group 1;" ::: "memory");
}
__device__ __forceinline__ void cp_wait0() {
    asm volatile("cp.async.wait_group 0;" ::: "memory");
}
__device__ __forceinline__ void ldsm4(uint32_t& r0, uint32_t& r1, uint32_t& r2,
                                      uint32_t& r3, uint32_t addr) {
    asm volatile("ldmatrix.sync.aligned.m8n8.x4.shared.b16 {%0,%1,%2,%3}, [%4];"
                 : "=r"(r0), "=r"(r1), "=r"(r2), "=r"(r3) : "r"(addr));
}
__device__ __forceinline__ void ldsm4t(uint32_t& r0, uint32_t& r1, uint32_t& r2,
                                       uint32_t& r3, uint32_t addr) {
    asm volatile("ldmatrix.sync.aligned.m8n8.x4.trans.shared.b16 {%0,%1,%2,%3}, [%4];"
                 : "=r"(r0), "=r"(r1), "=r"(r2), "=r"(r3) : "r"(addr));
}
__device__ __forceinline__ void hmma(float* d, const uint32_t* a,
                                     const uint32_t* b) {
    asm volatile(
        "mma.sync.aligned.m16n8k16.row.col.f32.f16.f16.f32 "
        "{%0,%1,%2,%3}, {%4,%5,%6,%7}, {%8,%9}, {%0,%1,%2,%3};"
        : "+f"(d[0]), "+f"(d[1]), "+f"(d[2]), "+f"(d[3])
        : "r"(a[0]), "r"(a[1]), "r"(a[2]), "r"(a[3]), "r"(b[0]), "r"(b[1]));
}
__device__ __forceinline__ uint32_t swz(uint32_t off) {
    return off ^ ((off >> 3) & 0x70u);
}

// ---------------- scaled-overlap split ----------------
__device__ __forceinline__ void split2(float x, __half& h, __half& m) {
    h = __float2half_rn(x);
    float hf = __half2float(h);
    m = __float2half_rn(fmaf(SPLIT_S - 1.f, x - hf, x));
}
__device__ __forceinline__ uint32_t pack2(__half a, __half b) {
    __half2 v = __halves2half2(a, b);
    return *reinterpret_cast<uint32_t*>(&v);
}

// ---------------- weight split kernels ----------------
__global__ __launch_bounds__(256) void split_kernel(
    const float4* __restrict__ in, __half* __restrict__ H,
    __half* __restrict__ M, int n4)
{
    int i = blockIdx.x * 256 + threadIdx.x;
    if (i >= n4) return;
    float4 v = in[i];
    __half h0,h1,h2,h3,m0,m1,m2,m3;
    split2(v.x, h0, m0); split2(v.y, h1, m1);
    split2(v.z, h2, m2); split2(v.w, h3, m3);
    ((__half2*)H)[2*i]   = __halves2half2(h0, h1);
    ((__half2*)H)[2*i+1] = __halves2half2(h2, h3);
    ((__half2*)M)[2*i]   = __halves2half2(m0, m1);
    ((__half2*)M)[2*i+1] = __halves2half2(m2, m3);
}

__global__ __launch_bounds__(256) void split_fc1_kernel(
    const float4* __restrict__ in, __half* __restrict__ H,
    __half* __restrict__ M, int n4)
{
    int i = blockIdx.x * 256 + threadIdx.x;
    if (i >= n4) return;
    float4 v = in[i];
    int row  = i >> 8;
    int cg   = i & 255;
    int layer = row / (2*DFFN);
    int r     = row - layer * (2*DFFN);
    int newr  = (r < DFFN) ? (2*r) : (2*(r - DFFN) + 1);
    size_t o  = ((size_t)layer * (2*DFFN) + newr) * 256 + cg;
    __half h0,h1,h2,h3,m0,m1,m2,m3;
    split2(v.x, h0, m0); split2(v.y, h1, m1);
    split2(v.z, h2, m2); split2(v.w, h3, m3);
    ((__half2*)H)[2*o]   = __halves2half2(h0, h1);
    ((__half2*)H)[2*o+1] = __halves2half2(h2, h3);
    ((__half2*)M)[2*o]   = __halves2half2(m0, m1);
    ((__half2*)M)[2*o+1] = __halves2half2(m2, m3);
}

// ---------------- fused (optional add) + RMSNorm -> f16 H/M -------------
__global__ __launch_bounds__(256) void add_rmsnorm_split(
    const float* __restrict__ A, const float* __restrict__ B,
    float* __restrict__ R, __half* __restrict__ OH,
    __half* __restrict__ OM, const float* __restrict__ w)
{
    int row = blockIdx.x;
    int t   = threadIdx.x;
    float4 v = ((const float4*)(A + (size_t)row*DIM))[t];
    if (B) {
        float4 bb = ((const float4*)(B + (size_t)row*DIM))[t];
        v.x += bb.x; v.y += bb.y; v.z += bb.z; v.w += bb.w;
    }
    ((float4*)(R + (size_t)row*DIM))[t] = v;

    float ss = v.x*v.x + v.y*v.y + v.z*v.z + v.w*v.w;
    #pragma unroll
    for (int o = 16; o; o >>= 1) ss += __shfl_xor_sync(~0u, ss, o);
    __shared__ float sred[8]; __shared__ float sinv;
    if ((t & 31) == 0) sred[t >> 5] = ss;
    __syncthreads();
    if (t == 0) {
        float s = 0.f;
        #pragma unroll
        for (int i = 0; i < 8; i++) s += sred[i];
        sinv = rsqrtf(s * (1.0f/DIM) + 1e-5f);
    }
    __syncthreads();
    float inv = sinv;
    float4 ww = ((const float4*)w)[t];
    float o0 = v.x*inv*ww.x, o1 = v.y*inv*ww.y, o2 = v.z*inv*ww.z, o3 = v.w*inv*ww.w;
    __half h0,h1,h2,h3,m0,m1,m2,m3;
    split2(o0,h0,m0); split2(o1,h1,m1); split2(o2,h2,m2); split2(o3,h3,m3);
    size_t base = (size_t)row*DIM + t*4;
    ((__half2*)(OH + base))[0] = __halves2half2(h0, h1);
    ((__half2*)(OH + base))[1] = __halves2half2(h2, h3);
    ((__half2*)(OM + base))[0] = __halves2half2(m0, m1);
    ((__half2*)(OM + base))[1] = __halves2half2(m2, m3);
}

// ---------------- final add + RMSNorm (fp32 out) ----------------
__global__ __launch_bounds__(256) void add_rmsnorm_f32(
    const float* __restrict__ A, const float* __restrict__ B,
    float* __restrict__ O, const float* __restrict__ w)
{
    int row = blockIdx.x;
    int t   = threadIdx.x;
    float4 v = ((const float4*)(A + (size_t)row*DIM))[t];
    float4 bb = ((const float4*)(B + (size_t)row*DIM))[t];
    v.x += bb.x; v.y += bb.y; v.z += bb.z; v.w += bb.w;

    float ss = v.x*v.x + v.y*v.y + v.z*v.z + v.w*v.w;
    #pragma unroll
    for (int o = 16; o; o >>= 1) ss += __shfl_xor_sync(~0u, ss, o);
    __shared__ float sred[8]; __shared__ float sinv;
    if ((t & 31) == 0) sred[t >> 5] = ss;
    __syncthreads();
    if (t == 0) {
        float s = 0.f;
        #pragma unroll
        for (int i = 0; i < 8; i++) s += sred[i];
        sinv = rsqrtf(s * (1.0f/DIM) + 1e-5f);
    }
    __syncthreads();
    float inv = sinv;
    float4 ww = ((const float4*)w)[t];
    float4 o;
    o.x = v.x*inv*ww.x; o.y = v.y*inv*ww.y; o.z = v.z*inv*ww.z; o.w = v.w*inv*ww.w;
    ((float4*)(O + (size_t)row*DIM))[t] = o;
}

// ---------------- HMMA GEMM: persistent-CTA, 2-term scaled-overlap split --
// R12 inner loop (512 thr, 16 warps 4m x 4n, warp tile 32x32, BK=64,
// 3-stage cp.async). Persistent: grid = min(tiles, 148); each CTA loops
// over tiles to eliminate wave quantization.
#define BM 128
#define BN 128
#define BK 64
#define GTHREADS 512
#define MAT_B (128*128)                // 16384 B per matrix tile
#define STAGE_B (4*MAT_B)              // 65536 B
#define GEMM_SMEM (3*STAGE_B)          // 196608 B

template<bool FUSE_SWIGLU>
__global__ __launch_bounds__(GTHREADS, 1) void gemm_2t(
    const __half* __restrict__ Ah, const __half* __restrict__ Am,
    const __half* __restrict__ Bh, const __half* __restrict__ Bm,
    float* __restrict__ C, __half* __restrict__ UH,
    __half* __restrict__ UM, int N, int K, int nbx, int ntiles)
{
    extern __shared__ __align__(128) char sm[];
    const uint32_t sb = smem_u32(sm);
    const int tid  = threadIdx.x;
    const int wid  = tid >> 5;
    const int lane = tid & 31;
    const int nchunk = K / BK;

    const int wm = (wid & 3) * 32;
    const int wn = (wid >> 2) * 32;

    const int a_row = (lane & 15);
    const int a_kof = ((lane >> 4) & 1) * 8;
    const int b_n   = (lane & 7) + ((lane >> 4) & 1) * 8;
    const int b_kof = ((lane >> 3) & 1) * 8;

    for (int tile = blockIdx.x; tile < ntiles; tile += gridDim.x) {
        const int bx = tile % nbx;
        const int by = tile / nbx;
        const int bm = by * BM;
        const int bn = bx * BN;

        float acc1[2][4][4], acc2[2][4][4];
        #pragma unroll
        for (int i = 0; i < 2; i++)
            #pragma unroll
            for (int j = 0; j < 4; j++)
                #pragma unroll
                for (int q = 0; q < 4; q++) { acc1[i][j][q] = 0.f; acc2[i][j][q] = 0.f; }

        auto load_stage = [&](int c, int s) {
            uint32_t st = sb + s * STAGE_B;
            int k0 = c * BK;
            #pragma unroll
            for (int j = 0; j < 2; j++) {
                int idx = tid + j * GTHREADS;
                int r = idx >> 3, cc = idx & 7;
                uint32_t off = swz((uint32_t)(r * 128 + cc * 16));
                size_t ga = (size_t)(bm + r) * K + k0 + cc * 8;
                size_t gb = (size_t)(bn + r) * K + k0 + cc * 8;
                cp16(st + off,           Ah + ga);
                cp16(st + MAT_B + off,   Am + ga);
                cp16(st + 2*MAT_B + off, Bh + gb);
                cp16(st + 3*MAT_B + off, Bm + gb);
            }
            cp_commit();
        };

        load_stage(0, 0);
        load_stage(1, 1);

        for (int c = 0; c < nchunk; c++) {
            int s = c % 3;
            if (c + 2 < nchunk) cp_wait1(); else cp_wait0();
            __syncthreads();
            if (c + 2 < nchunk) load_stage(c + 2, (c + 2) % 3);

            uint32_t st = sb + s * STAGE_B;
            const uint32_t sAh = st;
            const uint32_t sAm = st + MAT_B;
            const uint32_t sBh = st + 2*MAT_B;
            const uint32_t sBm = st + 3*MAT_B;

            #pragma unroll
            for (int k16 = 0; k16 < 4; k16++) {
                int kb = k16 * 16;
                uint32_t ah[2][4], am[2][4], bh[2][4], bmr[2][4];
                #pragma unroll
                for (int mt = 0; mt < 2; mt++) {
                    uint32_t off = swz((uint32_t)((wm + mt*16 + a_row) * 128
                                                  + (kb + a_kof) * 2));
                    ldsm4(ah[mt][0], ah[mt][1], ah[mt][2], ah[mt][3], sAh + off);
                    ldsm4(am[mt][0], am[mt][1], am[mt][2], am[mt][3], sAm + off);
                }
                #pragma unroll
                for (int np = 0; np < 2; np++) {
                    uint32_t off = swz((uint32_t)((wn + np*16 + b_n) * 128
                                                  + (kb + b_kof) * 2));
                    ldsm4(bh[np][0], bh[np][1], bh[np][2], bh[np][3], sBh + off);
                    ldsm4(bmr[np][0], bmr[np][1], bmr[np][2], bmr[np][3], sBm + off);
                }
                #pragma unroll
                for (int mt = 0; mt < 2; mt++)
                    #pragma unroll
                    for (int np = 0; np < 2; np++) {
                        hmma(acc1[mt][2*np],   ah[mt], &bh[np][0]);
                        hmma(acc1[mt][2*np+1], ah[mt], &bh[np][2]);
                    }
                #pragma unroll
                for (int mt = 0; mt < 2; mt++)
                    #pragma unroll
                    for (int np = 0; np < 2; np++) {
                        hmma(acc2[mt][2*np],   am[mt], &bmr[np][0]);
                        hmma(acc2[mt][2*np+1], am[mt], &bmr[np][2]);
                    }
            }
        }

        #pragma unroll
        for (int mt = 0; mt < 2; mt++)
            #pragma unroll
            for (int nt = 0; nt < 4; nt++)
                #pragma unroll
                for (int q = 0; q < 4; q++)
                    acc1[mt][nt][q] += (acc2[mt][nt][q] - acc1[mt][nt][q]) * SPLIT_INV;

        if (!FUSE_SWIGLU) {
            int r0 = bm + wm + (lane >> 2);
            int cc = bn + wn + (lane & 3) * 2;
            #pragma unroll
            for (int mt = 0; mt < 2; mt++) {
                #pragma unroll
                for (int nt = 0; nt < 4; nt++) {
                    float* p0 = C + (size_t)(r0 + mt*16) * N + cc + nt*8;
                    float* p1 = p0 + 8 * N;
                    *(float2*)p0 = make_float2(acc1[mt][nt][0], acc1[mt][nt][1]);
                    *(float2*)p1 = make_float2(acc1[mt][nt][2], acc1[mt][nt][3]);
                }
            }
        } else {
            int r0 = bm + wm + (lane >> 2);
            int uc = ((bn + wn) >> 1) + (lane & 3);
            int UW = N >> 1;
            #pragma unroll
            for (int mt = 0; mt < 2; mt++) {
                #pragma unroll
                for (int nt = 0; nt < 4; nt++) {
                    int col = uc + nt*4;
                    {
                        float a0 = acc1[mt][nt][0], a1 = acc1[mt][nt][1];
                        float sgl = (a0 / (1.f + expf(-a0))) * a1;
                        __half h, m;
                        split2(sgl, h, m);
                        size_t o = (size_t)(r0 + mt*16) * UW + col;
                        UH[o] = h; UM[o] = m;
                    }
                    {
                        float a0 = acc1[mt][nt][2], a1 = acc1[mt][nt][3];
                        float sgl = (a0 / (1.f + expf(-a0))) * a1;
                        __half h, m;
                        split2(sgl, h, m);
                        size_t o = (size_t)(r0 + mt*16 + 8) * UW + col;
                        UH[o] = h; UM[o] = m;
                    }
                }
            }
        }
        __syncthreads();   // stages reused next tile
    }
}

// ---------------- RoPE + head-major f16 split of q,k,v ----------------
__global__ __launch_bounds__(256) void rope_split_kernel(
    const float* __restrict__ qkv,
    __half* __restrict__ Qh, __half* __restrict__ Qm,
    __half* __restrict__ Kh, __half* __restrict__ Km,
    __half* __restrict__ Vh, __half* __restrict__ Vm)
{
    int idx = blockIdx.x * blockDim.x + threadIdx.x;
    int j   = idx & 31;
    int h   = (idx >> 5) & (NHEAD-1);
    int pos = (idx >> 9) & (SEQ-1);
    int b   = idx >> 20;

    float inv = expf(-(float)j * (9.210340371976184f / 32.f));
    float fr  = (float)pos * inv;
    float s, c;
    sincosf(fr, &s, &c);

    size_t base = (size_t)(b*SEQ + pos) * (3*DIM) + h*DHEAD + j;
    float q1 = qkv[base], q2 = qkv[base+32];
    float k1 = qkv[base+DIM], k2 = qkv[base+DIM+32];
    float v1 = qkv[base+2*DIM], v2 = qkv[base+2*DIM+32];
    float qr1 = q1*c - q2*s, qr2 = q2*c + q1*s;
    float kr1 = k1*c - k2*s, kr2 = k2*c + k1*s;

    size_t o = ((size_t)(b*NHEAD + h)*SEQ + pos) * DHEAD + j;
    __half hh, mm;
    split2(qr1, hh, mm); Qh[o] = hh;    Qm[o] = mm;
    split2(qr2, hh, mm); Qh[o+32] = hh; Qm[o+32] = mm;
    split2(kr1, hh, mm); Kh[o] = hh;    Km[o] = mm;
    split2(kr2, hh, mm); Kh[o+32] = hh; Km[o+32] = mm;
    split2(v1,  hh, mm); Vh[o] = hh;    Vm[o] = mm;
    split2(v2,  hh, mm); Vh[o+32] = hh; Vm[o+32] = mm;
}

// ---------------- tensor-core windowed flash attention ----------------
#define AQT 64
#define AKT 32
#define ATT_SMEM (16384 + 2*16384)

__global__ __launch_bounds__(128) void attn_tc(
    const __half* __restrict__ Qh, const __half* __restrict__ Qm,
    const __half* __restrict__ Kh, const __half* __restrict__ Km,
    const __half* __restrict__ Vh, const __half* __restrict__ Vm,
    __half* __restrict__ cxH, __half* __restrict__ cxM)
{
    extern __shared__ __align__(128) char sm[];
    const uint32_t sb = smem_u32(sm);
    const int tid = threadIdx.x;
    const int w = tid >> 5, lane = tid & 31;
    const int qt0 = blockIdx.x * AQT;
    const int hh = blockIdx.y, b = blockIdx.z;
    const size_t hb = ((size_t)(b*NHEAD + hh)) * SEQ * DHEAD;

    #pragma unroll
    for (int t = 0; t < 4; t++) {
        int i = tid + t*128;
        int r = i >> 3, c = i & 7;
        uint32_t off = swz((uint32_t)(r*128 + c*16));
        size_t g = hb + (size_t)(qt0 + r)*DHEAD + c*8;
        cp16(sb + off,        Qh + g);
        cp16(sb + 8192 + off, Qm + g);
    }
    cp_commit();

    int kstart = qt0 - (WIN-1);
    if (kstart < 0) kstart = 0;
    kstart &= ~(AKT-1);
    const int kend = qt0 + AQT;
    const int niter = (kend - kstart) / AKT;

    auto load_kv = [&](int kt, int s) {
        uint32_t st = sb + 16384 + s*16384;
        #pragma unroll
        for (int t = 0; t < 2; t++) {
            int i = tid + t*128;
            int r = i >> 3, c = i & 7;
            uint32_t off = swz((uint32_t)(r*128 + c*16));
            size_t g = hb + (size_t)(kt + r)*DHEAD + c*8;
            cp16(st + off,         Kh + g);
            cp16(st + 4096 + off,  Km + g);
            cp16(st + 8192 + off,  Vh + g);
            cp16(st + 12288 + off, Vm + g);
        }
        cp_commit();
    };
    load_kv(kstart, 0);

    uint32_t aQh[4][4], aQm[4][4];
    float accC1[8][4], accC2[8][4];
    #pragma unroll
    for (int j = 0; j < 8; j++)
        #pragma unroll
        for (int q = 0; q < 4; q++) { accC1[j][q] = 0.f; accC2[j][q] = 0.f; }
    float m0 = -INFINITY, m1 = -INFINITY, l0 = 0.f, l1 = 0.f;
    const int qrow0 = qt0 + w*16 + (lane >> 2);
    const int qrow1 = qrow0 + 8;
    const int a_row = lane & 15;
    const int kofb  = ((lane >> 4) & 1) * 16;
    const int krow  = (lane & 7) + ((lane >> 3) & 1) * 8;
    const int bcolb = ((lane >> 4) & 1) * 16;
    const int kbrow = (lane & 7) + ((lane >> 4) & 1) * 8;
    const int kbcol = ((lane >> 3) & 1) * 16;

    for (int it = 0; it < niter; it++) {
        int kt = kstart + it * AKT;
        int s = it & 1;
        if (it + 1 < niter) { load_kv(kt + AKT, s ^ 1); cp_wait1(); }
        else cp_wait0();
        __syncthreads();

        if (it == 0) {
            #pragma unroll
            for (int kc = 0; kc < 4; kc++) {
                uint32_t off = swz((uint32_t)((w*16 + a_row)*128 + kc*32 + kofb));
                ldsm4(aQh[kc][0], aQh[kc][1], aQh[kc][2], aQh[kc][3], sb + off);
                ldsm4(aQm[kc][0], aQm[kc][1], aQm[kc][2], aQm[kc][3], sb + 8192 + off);
            }
        }

        uint32_t st  = sb + 16384 + s*16384;
        uint32_t sKh = st, sKm = st + 4096, sVh = st + 8192, sVm = st + 12288;

        float s1[4][4], s2[4][4];
        #pragma unroll
        for (int j = 0; j < 4; j++)
            #pragma unroll
            for (int q = 0; q < 4; q++) { s1[j][q] = 0.f; s2[j][q] = 0.f; }
        #pragma unroll
        for (int kc = 0; kc < 4; kc++) {
            uint32_t off0 = swz((uint32_t)((kbrow)*128      + kc*32 + kbcol));
            uint32_t off1 = swz((uint32_t)((16 + kbrow)*128 + kc*32 + kbcol));
            uint32_t kh0[4], kh1[4], km0[4], km1[4];
            ldsm4(kh0[0], kh0[1], kh0[2], kh0[3], sKh + off0);
            ldsm4(kh1[0], kh1[1], kh1[2], kh1[3], sKh + off1);
            ldsm4(km0[0], km0[1], km0[2], km0[3], sKm + off0);
            ldsm4(km1[0], km1[1], km1[2], km1[3], sKm + off1);
            hmma(s1[0], aQh[kc], &kh0[0]); hmma(s1[1], aQh[kc], &kh0[2]);
            hmma(s1[2], aQh[kc], &kh1[0]); hmma(s1[3], aQh[kc], &kh1[2]);
            hmma(s2[0], aQm[kc], &km0[0]); hmma(s2[1], aQm[kc], &km0[2]);
            hmma(s2[2], aQm[kc], &km1[0]); hmma(s2[3], aQm[kc], &km1[2]);
        }

        float pv0[8], pv1[8];
        float tmax0 = -INFINITY, tmax1 = -INFINITY;
        #pragma unroll
        for (int j = 0; j < 4; j++) {
            int kc0 = kt + j*8 + 2*(lane & 3);
            #pragma unroll
            for (int e = 0; e < 2; e++) {
                int kk = kc0 + e;
                float v = s1[j][e] + (s2[j][e] - s1[j][e]) * SPLIT_INV;
                v *= 0.125f;
                v = (kk <= qrow0 && kk >= qrow0 - (WIN-1)) ? v : -INFINITY;
                pv0[j*2+e] = v; tmax0 = fmaxf(tmax0, v);
                float u = s1[j][2+e] + (s2[j][2+e] - s1[j][2+e]) * SPLIT_INV;
                u *= 0.125f;
                u = (kk <= qrow1 && kk >= qrow1 - (WIN-1)) ? u : -INFINITY;
                pv1[j*2+e] = u; tmax1 = fmaxf(tmax1, u);
            }
        }
        tmax0 = fmaxf(tmax0, __shfl_xor_sync(~0u, tmax0, 1));
        tmax0 = fmaxf(tmax0, __shfl_xor_sync(~0u, tmax0, 2));
        tmax1 = fmaxf(tmax1, __shfl_xor_sync(~0u, tmax1, 1));
        tmax1 = fmaxf(tmax1, __shfl_xor_sync(~0u, tmax1, 2));
        float mn0 = fmaxf(m0, tmax0), mn1 = fmaxf(m1, tmax1);
        bool dead0 = (mn0 == -INFINITY), dead1 = (mn1 == -INFINITY);
        float corr0 = dead0 ? 1.f : __expf(m0 - mn0);
        float corr1 = dead1 ? 1.f : __expf(m1 - mn1);
        float sum0 = 0.f, sum1 = 0.f;
        #pragma unroll
        for (int i = 0; i < 8; i++) {
            float p0 = dead0 ? 0.f : __expf(pv0[i] - mn0);
            float p1 = dead1 ? 0.f : __expf(pv1[i] - mn1);
            pv0[i] = p0; pv1[i] = p1;
            sum0 += p0; sum1 += p1;
        }
        sum0 += __shfl_xor_sync(~0u, sum0, 1);
        sum0 += __shfl_xor_sync(~0u, sum0, 2);
        sum1 += __shfl_xor_sync(~0u, sum1, 1);
        sum1 += __shfl_xor_sync(~0u, sum1, 2);
        l0 = l0 * corr0 + sum0; m0 = mn0;
        l1 = l1 * corr1 + sum1; m1 = mn1;
        #pragma unroll
        for (int j = 0; j < 8; j++) {
            accC1[j][0] *= corr0; accC1[j][1] *= corr0;
            accC1[j][2] *= corr1; accC1[j][3] *= corr1;
            accC2[j][0] *= corr0; accC2[j][1] *= corr0;
            accC2[j][2] *= corr1; accC2[j][3] *= corr1;
        }

        #pragma unroll
        for (int kc2 = 0; kc2 < 2; kc2++) {
            uint32_t aPh[4], aPm[4];
            {
                __half h0,mh0,h1,mh1;
                split2(pv0[kc2*4+0], h0, mh0); split2(pv0[kc2*4+1], h1, mh1);
                aPh[0] = pack2(h0, h1); aPm[0] = pack2(mh0, mh1);
                split2(pv1[kc2*4+0], h0, mh0); split2(pv1[kc2*4+1], h1, mh1);
                aPh[1] = pack2(h0, h1); aPm[1] = pack2(mh0, mh1);
                split2(pv0[kc2*4+2], h0, mh0); split2(pv0[kc2*4+3], h1, mh1);
                aPh[2] = pack2(h0, h1); aPm[2] = pack2(mh0, mh1);
                split2(pv1[kc2*4+2], h0, mh0); split2(pv1[kc2*4+3], h1, mh1);
                aPh[3] = pack2(h0, h1); aPm[3] = pack2(mh0, mh1);
            }
            int vrow = kc2*16 + krow;
            #pragma unroll
            for (int dc = 0; dc < 4; dc++) {
                uint32_t off = swz((uint32_t)(vrow*128 + dc*32 + bcolb));
                uint32_t vh[4], vm[4];
                ldsm4t(vh[0], vh[1], vh[2], vh[3], sVh + off);
                ldsm4t(vm[0], vm[1], vm[2], vm[3], sVm + off);
                hmma(accC1[dc*2+0], aPh, &vh[0]); hmma(accC1[dc*2+1], aPh, &vh[2]);
                hmma(accC2[dc*2+0], aPm, &vm[0]); hmma(accC2[dc*2+1], aPm, &vm[2]);
            }
        }
        __syncthreads();
    }

    float invl0 = 1.f / l0, invl1 = 1.f / l1;
    #pragma unroll
    for (int j = 0; j < 8; j++) {
        float c0 = accC1[j][0] + (accC2[j][0] - accC1[j][0]) * SPLIT_INV;
        float c1 = accC1[j][1] + (accC2[j][1] - accC1[j][1]) * SPLIT_INV;
        float c2 = accC1[j][2] + (accC2[j][2] - accC1[j][2]) * SPLIT_INV;
        float c3 = accC1[j][3] + (accC2[j][3] - accC1[j][3]) * SPLIT_INV;
        c0 *= invl0; c1 *= invl0; c2 *= invl1; c3 *= invl1;
        int dh = hh*DHEAD + j*8 + 2*(lane & 3);
        size_t a0 = (size_t)(b*SEQ + qrow0)*DIM + dh;
        size_t a1 = (size_t)(b*SEQ + qrow1)*DIM + dh;
        __half h0,mm0,h1,mm1;
        split2(c0, h0, mm0); split2(c1, h1, mm1);
        *(__half2*)(cxH + a0) = __halves2half2(h0, h1);
        *(__half2*)(cxM + a0) = __halves2half2(mm0, mm1);
        split2(c2, h0, mm0); split2(c3, h1, mm1);
        *(__half2*)(cxH + a1) = __halves2half2(h0, h1);
        *(__half2*)(cxM + a1) = __halves2half2(mm0, mm1);
    }
}

// ---------------- host orchestration ----------------
static inline int pgrid(int ntiles) { return ntiles < NSM ? ntiles : NSM; }

extern "C" void kernel_launch(void* const* d_in, const int* in_sizes, int n_in,
                              void* d_out, int out_size)
{
    const float* x_in = (const float*)d_in[0];
    const float* Wqkv = (const float*)d_in[2];
    const float* Wout = (const float*)d_in[3];
    const float* fc1  = (const float*)d_in[4];
    const float* fc2  = (const float*)d_in[5];
    const float* n1w  = (const float*)d_in[6];
    const float* n2w  = (const float*)d_in[7];
    const float* fnw  = (const float*)d_in[8];
    float* out = (float*)d_out;

    float *res, *qkv, *aab, *xx;
    __half *hnH, *hnM, *cxH, *cxM, *uH, *uM;
    __half *qkvH, *qkvM, *woH, *woM, *f1H, *f1M, *f2H, *f2M;
    __half *Qh, *Qm, *Kh, *Km, *Vh, *Vm;

    cudaGetSymbolAddress((void**)&res, g_res);
    cudaGetSymbolAddress((void**)&qkv, g_qkv);
    cudaGetSymbolAddress((void**)&aab, g_a);
    cudaGetSymbolAddress((void**)&xx,  g_x);
    cudaGetSymbolAddress((void**)&hnH, g_hnH);
    cudaGetSymbolAddress((void**)&hnM, g_hnM);
    cudaGetSymbolAddress((void**)&cxH, g_cxH);
    cudaGetSymbolAddress((void**)&cxM, g_cxM);
    cudaGetSymbolAddress((void**)&uH,  g_uH);
    cudaGetSymbolAddress((void**)&uM,  g_uM);
    cudaGetSymbolAddress((void**)&qkvH, g_qkvH);
    cudaGetSymbolAddress((void**)&qkvM, g_qkvM);
    cudaGetSymbolAddress((void**)&woH,  g_woH);
    cudaGetSymbolAddress((void**)&woM,  g_woM);
    cudaGetSymbolAddress((void**)&f1H,  g_f1H);
    cudaGetSymbolAddress((void**)&f1M,  g_f1M);
    cudaGetSymbolAddress((void**)&f2H,  g_f2H);
    cudaGetSymbolAddress((void**)&f2M,  g_f2M);
    cudaGetSymbolAddress((void**)&Qh, g_Qh);
    cudaGetSymbolAddress((void**)&Qm, g_Qm);
    cudaGetSymbolAddress((void**)&Kh, g_Kh);
    cudaGetSymbolAddress((void**)&Km, g_Km);
    cudaGetSymbolAddress((void**)&Vh, g_Vh);
    cudaGetSymbolAddress((void**)&Vm, g_Vm);

    cudaFuncSetAttribute(gemm_2t<false>, cudaFuncAttributeMaxDynamicSharedMemorySize, GEMM_SMEM);
    cudaFuncSetAttribute(gemm_2t<true>,  cudaFuncAttributeMaxDynamicSharedMemorySize, GEMM_SMEM);
    cudaFuncSetAttribute(attn_tc, cudaFuncAttributeMaxDynamicSharedMemorySize, ATT_SMEM);

    const int nbx_qkv = 3*DIM/BN,  nby = MROWS/BM;          // 24 x 32
    const int nt_qkv  = nbx_qkv * nby;                       // 768
    const int nbx_d   = DIM/BN;                              // 8
    const int nt_d    = nbx_d * nby;                          // 256
    const int nbx_f1  = 2*DFFN/BN;                            // 64
    const int nt_f1   = nbx_f1 * nby;                          // 2048

    // launches 0..2, QKV GEMM at index 3 (ncu capture target)
    add_rmsnorm_split<<<MROWS, 256>>>(x_in, (const float*)nullptr,
                                      res, hnH, hnM, n1w);
    {
        int n4 = NLAYER*3*DIM*DIM/4;
        split_kernel<<<(n4+255)/256, 256>>>((const float4*)Wqkv, qkvH, qkvM, n4);
        n4 = NLAYER*DIM*DIM/4;
        split_kernel<<<(n4+255)/256, 256>>>((const float4*)Wout, woH, woM, n4);
    }

    for (int l = 0; l < NLAYER; l++) {
        if (l > 0)
            add_rmsnorm_split<<<MROWS, 256>>>(xx, res, res, hnH, hnM,
                                              n1w + (size_t)l*DIM);

        gemm_2t<false><<<pgrid(nt_qkv), GTHREADS, GEMM_SMEM>>>(
            hnH, hnM,
            qkvH + (size_t)l*3*DIM*DIM, qkvM + (size_t)l*3*DIM*DIM,
            qkv, nullptr, nullptr, 3*DIM, DIM, nbx_qkv, nt_qkv);

        if (l == 0) {
            int n4 = NLAYER*2*DFFN*DIM/4;
            split_fc1_kernel<<<(n4+255)/256, 256>>>((const float4*)fc1, f1H, f1M, n4);
            n4 = NLAYER*DIM*DFFN/4;
            split_kernel<<<(n4+255)/256, 256>>>((const float4*)fc2, f2H, f2M, n4);
        }

        rope_split_kernel<<<(BATCH*SEQ*NHEAD*32)/256, 256>>>(
            qkv, Qh, Qm, Kh, Km, Vh, Vm);

        attn_tc<<<dim3(SEQ/AQT, NHEAD, BATCH), 128, ATT_SMEM>>>(
            Qh, Qm, Kh, Km, Vh, Vm, cxH, cxM);

        gemm_2t<false><<<pgrid(nt_d), GTHREADS, GEMM_SMEM>>>(
            cxH, cxM,
            woH + (size_t)l*DIM*DIM, woM + (size_t)l*DIM*DIM,
            aab, nullptr, nullptr, DIM, DIM, nbx_d, nt_d);

        add_rmsnorm_split<<<MROWS, 256>>>(aab, res, res, hnH, hnM,
                                          n2w + (size_t)l*DIM);

        gemm_2t<true><<<pgrid(nt_f1), GTHREADS, GEMM_SMEM>>>(
            hnH, hnM,
            f1H + (size_t)l*2*DFFN*DIM, f1M + (size_t)l*2*DFFN*DIM,
            nullptr, uH, uM, 2*DFFN, DIM, nbx_f1, nt_f1);

        gemm_2t<false><<<pgrid(nt_d), GTHREADS, GEMM_SMEM>>>(
            uH, uM,
            f2H + (size_t)l*DIM*DFFN, f2M + (size_t)l*DIM*DFFN,
            xx, nullptr, nullptr, DIM, DFFN, nbx_d, nt_d);
    }

    add_rmsnorm_f32<<<MROWS, 256>>>(xx, res, out, fnw);
}

// round 16
// speedup vs baseline: 1.0961x; 1.0961x over previous
#include <cuda_runtime.h>
#include <cuda_fp16.h>
#include <math.h>
#include <stdint.h>

#define BATCH   2
#define SEQ     2048
#define DIM     1024
#define NHEAD   16
#define DHEAD   64
#define NLAYER  8
#define DFFN    4096
#define WIN     1024
#define MROWS   (BATCH*SEQ)   // 4096
#define SPLIT_S 128.f
#define SPLIT_INV 0.0078125f   // 1/128

// ---------------- scratch (device globals; no allocations) ----------------
__device__ float g_res[MROWS*DIM];
__device__ float g_qkv[MROWS*3*DIM];
__device__ float g_a  [MROWS*DIM];
__device__ float g_x  [MROWS*DIM];

__device__ __half g_hnH [MROWS*DIM];
__device__ __half g_hnM [MROWS*DIM];
__device__ __half g_cxH [MROWS*DIM];
__device__ __half g_cxM [MROWS*DIM];
__device__ __half g_uH  [MROWS*DFFN];
__device__ __half g_uM  [MROWS*DFFN];

// head-major f16 splits for attention
#define AHE (BATCH*NHEAD*SEQ*DHEAD)
__device__ __half g_Qh[AHE];
__device__ __half g_Qm[AHE];
__device__ __half g_Kh[AHE];
__device__ __half g_Km[AHE];
__device__ __half g_Vh[AHE];
__device__ __half g_Vm[AHE];

__device__ __half g_qkvH[NLAYER*3*DIM*DIM];
__device__ __half g_qkvM[NLAYER*3*DIM*DIM];
__device__ __half g_woH [NLAYER*DIM*DIM];
__device__ __half g_woM [NLAYER*DIM*DIM];
__device__ __half g_f1H [NLAYER*2*DFFN*DIM];   // interleaved rows
__device__ __half g_f1M [NLAYER*2*DFFN*DIM];
__device__ __half g_f2H [NLAYER*DIM*DFFN];
__device__ __half g_f2M [NLAYER*DIM*DFFN];

// ---------------- PTX helpers ----------------
__device__ __forceinline__ uint32_t smem_u32(const void* p) {
    uint32_t a;
    asm("{ .reg .u64 t; cvta.to.shared.u64 t, %1; cvt.u32.u64 %0, t; }"
        : "=r"(a) : "l"(p));
    return a;
}
__device__ __forceinline__ void cp16(uint32_t dst, const void* src) {
    asm volatile("cp.async.cg.shared.global [%0], [%1], 16;"
                 :: "r"(dst), "l"(src) : "memory");
}
__device__ __forceinline__ void cp_commit() {
    asm volatile("cp.async.commit_group;" ::: "memory");
}
__device__ __forceinline__ void cp_wait1() {
    asm volatile("cp.async.wait_group 1;" ::: "memory");
}
__device__ __forceinline__ void cp_wait0() {
    asm volatile("cp.async.wait_group 0;" ::: "memory");
}
__device__ __forceinline__ void ldsm4(uint32_t& r0, uint32_t& r1, uint32_t& r2,
                                      uint32_t& r3, uint32_t addr) {
    asm volatile("ldmatrix.sync.aligned.m8n8.x4.shared.b16 {%0,%1,%2,%3}, [%4];"
                 : "=r"(r0), "=r"(r1), "=r"(r2), "=r"(r3) : "r"(addr));
}
__device__ __forceinline__ void ldsm4t(uint32_t& r0, uint32_t& r1, uint32_t& r2,
                                       uint32_t& r3, uint32_t addr) {
    asm volatile("ldmatrix.sync.aligned.m8n8.x4.trans.shared.b16 {%0,%1,%2,%3}, [%4];"
                 : "=r"(r0), "=r"(r1), "=r"(r2), "=r"(r3) : "r"(addr));
}
__device__ __forceinline__ void hmma(float* d, const uint32_t* a,
                                     const uint32_t* b) {
    asm volatile(
        "mma.sync.aligned.m16n8k16.row.col.f32.f16.f16.f32 "
        "{%0,%1,%2,%3}, {%4,%5,%6,%7}, {%8,%9}, {%0,%1,%2,%3};"
        : "+f"(d[0]), "+f"(d[1]), "+f"(d[2]), "+f"(d[3])
        : "r"(a[0]), "r"(a[1]), "r"(a[2]), "r"(a[3]), "r"(b[0]), "r"(b[1]));
}
__device__ __forceinline__ uint32_t swz(uint32_t off) {
    return off ^ ((off >> 3) & 0x70u);
}

// ---------------- scaled-overlap split ----------------
__device__ __forceinline__ void split2(float x, __half& h, __half& m) {
    h = __float2half_rn(x);
    float hf = __half2float(h);
    m = __float2half_rn(fmaf(SPLIT_S - 1.f, x - hf, x));
}
__device__ __forceinline__ uint32_t pack2(__half a, __half b) {
    __half2 v = __halves2half2(a, b);
    return *reinterpret_cast<uint32_t*>(&v);
}

// ---------------- weight split kernels ----------------
__global__ __launch_bounds__(256) void split_kernel(
    const float4* __restrict__ in, __half* __restrict__ H,
    __half* __restrict__ M, int n4)
{
    int i = blockIdx.x * 256 + threadIdx.x;
    if (i >= n4) return;
    float4 v = in[i];
    __half h0,h1,h2,h3,m0,m1,m2,m3;
    split2(v.x, h0, m0); split2(v.y, h1, m1);
    split2(v.z, h2, m2); split2(v.w, h3, m3);
    ((__half2*)H)[2*i]   = __halves2half2(h0, h1);
    ((__half2*)H)[2*i+1] = __halves2half2(h2, h3);
    ((__half2*)M)[2*i]   = __halves2half2(m0, m1);
    ((__half2*)M)[2*i+1] = __halves2half2(m2, m3);
}

__global__ __launch_bounds__(256) void split_fc1_kernel(
    const float4* __restrict__ in, __half* __restrict__ H,
    __half* __restrict__ M, int n4)
{
    int i = blockIdx.x * 256 + threadIdx.x;
    if (i >= n4) return;
    float4 v = in[i];
    int row  = i >> 8;
    int cg   = i & 255;
    int layer = row / (2*DFFN);
    int r     = row - layer * (2*DFFN);
    int newr  = (r < DFFN) ? (2*r) : (2*(r - DFFN) + 1);
    size_t o  = ((size_t)layer * (2*DFFN) + newr) * 256 + cg;
    __half h0,h1,h2,h3,m0,m1,m2,m3;
    split2(v.x, h0, m0); split2(v.y, h1, m1);
    split2(v.z, h2, m2); split2(v.w, h3, m3);
    ((__half2*)H)[2*o]   = __halves2half2(h0, h1);
    ((__half2*)H)[2*o+1] = __halves2half2(h2, h3);
    ((__half2*)M)[2*o]   = __halves2half2(m0, m1);
    ((__half2*)M)[2*o+1] = __halves2half2(m2, m3);
}

// ---------------- fused (optional add) + RMSNorm -> f16 H/M -------------
__global__ __launch_bounds__(256) void add_rmsnorm_split(
    const float* __restrict__ A, const float* __restrict__ B,
    float* __restrict__ R, __half* __restrict__ OH,
    __half* __restrict__ OM, const float* __restrict__ w)
{
    int row = blockIdx.x;
    int t   = threadIdx.x;
    float4 v = ((const float4*)(A + (size_t)row*DIM))[t];
    if (B) {
        float4 bb = ((const float4*)(B + (size_t)row*DIM))[t];
        v.x += bb.x; v.y += bb.y; v.z += bb.z; v.w += bb.w;
    }
    ((float4*)(R + (size_t)row*DIM))[t] = v;

    float ss = v.x*v.x + v.y*v.y + v.z*v.z + v.w*v.w;
    #pragma unroll
    for (int o = 16; o; o >>= 1) ss += __shfl_xor_sync(~0u, ss, o);
    __shared__ float sred[8]; __shared__ float sinv;
    if ((t & 31) == 0) sred[t >> 5] = ss;
    __syncthreads();
    if (t == 0) {
        float s = 0.f;
        #pragma unroll
        for (int i = 0; i < 8; i++) s += sred[i];
        sinv = rsqrtf(s * (1.0f/DIM) + 1e-5f);
    }
    __syncthreads();
    float inv = sinv;
    float4 ww = ((const float4*)w)[t];
    float o0 = v.x*inv*ww.x, o1 = v.y*inv*ww.y, o2 = v.z*inv*ww.z, o3 = v.w*inv*ww.w;
    __half h0,h1,h2,h3,m0,m1,m2,m3;
    split2(o0,h0,m0); split2(o1,h1,m1); split2(o2,h2,m2); split2(o3,h3,m3);
    size_t base = (size_t)row*DIM + t*4;
    ((__half2*)(OH + base))[0] = __halves2half2(h0, h1);
    ((__half2*)(OH + base))[1] = __halves2half2(h2, h3);
    ((__half2*)(OM + base))[0] = __halves2half2(m0, m1);
    ((__half2*)(OM + base))[1] = __halves2half2(m2, m3);
}

// ---------------- final add + RMSNorm (fp32 out) ----------------
__global__ __launch_bounds__(256) void add_rmsnorm_f32(
    const float* __restrict__ A, const float* __restrict__ B,
    float* __restrict__ O, const float* __restrict__ w)
{
    int row = blockIdx.x;
    int t   = threadIdx.x;
    float4 v = ((const float4*)(A + (size_t)row*DIM))[t];
    float4 bb = ((const float4*)(B + (size_t)row*DIM))[t];
    v.x += bb.x; v.y += bb.y; v.z += bb.z; v.w += bb.w;

    float ss = v.x*v.x + v.y*v.y + v.z*v.z + v.w*v.w;
    #pragma unroll
    for (int o = 16; o; o >>= 1) ss += __shfl_xor_sync(~0u, ss, o);
    __shared__ float sred[8]; __shared__ float sinv;
    if ((t & 31) == 0) sred[t >> 5] = ss;
    __syncthreads();
    if (t == 0) {
        float s = 0.f;
        #pragma unroll
        for (int i = 0; i < 8; i++) s += sred[i];
        sinv = rsqrtf(s * (1.0f/DIM) + 1e-5f);
    }
    __syncthreads();
    float inv = sinv;
    float4 ww = ((const float4*)w)[t];
    float4 o;
    o.x = v.x*inv*ww.x; o.y = v.y*inv*ww.y; o.z = v.z*inv*ww.z; o.w = v.w*inv*ww.w;
    ((float4*)(O + (size_t)row*DIM))[t] = o;
}

// ---------------- HMMA GEMM: C = A @ B^T, 2-term scaled-overlap split ----
// 2 CTAs/SM: 256 threads, 8 warps (4m x 2n), warp tile 32x32, BM=128, BN=64,
// BK=64, double-buffered cp.async (96KB smem/CTA). Independent CTAs cover
// each other's barrier/pipeline-refill bubbles.
#define BM 128
#define BN 64
#define BK 64
#define GTHREADS 256
#define MAT_A (128*128)                // 16384 B per A split tile
#define MAT_BB (64*128)                // 8192 B per B split tile
#define STAGE_B (2*MAT_A + 2*MAT_BB)   // 49152 B
#define GEMM_SMEM (2*STAGE_B)          // 98304 B

template<bool FUSE_SWIGLU>
__global__ __launch_bounds__(GTHREADS, 2) void gemm_2t(
    const __half* __restrict__ Ah, const __half* __restrict__ Am,
    const __half* __restrict__ Bh, const __half* __restrict__ Bm,
    float* __restrict__ C, __half* __restrict__ UH,
    __half* __restrict__ UM, int N, int K)
{
    extern __shared__ __align__(128) char sm[];
    const uint32_t sb = smem_u32(sm);
    const int tid  = threadIdx.x;
    const int wid  = tid >> 5;
    const int lane = tid & 31;
    const int bm = blockIdx.y * BM;
    const int bn = blockIdx.x * BN;
    const int nchunk = K / BK;

    const int wm = (wid & 3) * 32;
    const int wn = (wid >> 2) * 32;

    const int a_row = (lane & 15);
    const int a_kof = ((lane >> 4) & 1) * 8;
    const int b_n   = (lane & 7) + ((lane >> 4) & 1) * 8;
    const int b_kof = ((lane >> 3) & 1) * 8;

    float acc1[2][4][4], acc2[2][4][4];
    #pragma unroll
    for (int i = 0; i < 2; i++)
        #pragma unroll
        for (int j = 0; j < 4; j++)
            #pragma unroll
            for (int q = 0; q < 4; q++) { acc1[i][j][q] = 0.f; acc2[i][j][q] = 0.f; }

    auto load_stage = [&](int c, int s) {
        uint32_t st = sb + s * STAGE_B;
        int k0 = c * BK;
        #pragma unroll
        for (int j = 0; j < 4; j++) {              // A: 128 rows x 8 chunks
            int idx = tid + j * GTHREADS;          // 0..1023
            int r = idx >> 3, cc = idx & 7;
            uint32_t off = swz((uint32_t)(r * 128 + cc * 16));
            size_t ga = (size_t)(bm + r) * K + k0 + cc * 8;
            cp16(st + off,         Ah + ga);
            cp16(st + MAT_A + off, Am + ga);
        }
        #pragma unroll
        for (int j = 0; j < 2; j++) {              // B: 64 rows x 8 chunks
            int idx = tid + j * GTHREADS;          // 0..511
            int r = idx >> 3, cc = idx & 7;
            uint32_t off = swz((uint32_t)(r * 128 + cc * 16));
            size_t gb = (size_t)(bn + r) * K + k0 + cc * 8;
            cp16(st + 2*MAT_A + off,          Bh + gb);
            cp16(st + 2*MAT_A + MAT_BB + off, Bm + gb);
        }
        cp_commit();
    };

    load_stage(0, 0);

    for (int c = 0; c < nchunk; c++) {
        int s = c & 1;
        cp_wait0();
        __syncthreads();
        if (c + 1 < nchunk) load_stage(c + 1, s ^ 1);

        uint32_t st = sb + s * STAGE_B;
        const uint32_t sAh = st;
        const uint32_t sAm = st + MAT_A;
        const uint32_t sBh = st + 2*MAT_A;
        const uint32_t sBm = st + 2*MAT_A + MAT_BB;

        #pragma unroll
        for (int k16 = 0; k16 < 4; k16++) {
            int kb = k16 * 16;
            uint32_t ah[2][4], am[2][4], bh[2][4], bmr[2][4];
            #pragma unroll
            for (int mt = 0; mt < 2; mt++) {
                uint32_t off = swz((uint32_t)((wm + mt*16 + a_row) * 128
                                              + (kb + a_kof) * 2));
                ldsm4(ah[mt][0], ah[mt][1], ah[mt][2], ah[mt][3], sAh + off);
                ldsm4(am[mt][0], am[mt][1], am[mt][2], am[mt][3], sAm + off);
            }
            #pragma unroll
            for (int np = 0; np < 2; np++) {
                uint32_t off = swz((uint32_t)((wn + np*16 + b_n) * 128
                                              + (kb + b_kof) * 2));
                ldsm4(bh[np][0], bh[np][1], bh[np][2], bh[np][3], sBh + off);
                ldsm4(bmr[np][0], bmr[np][1], bmr[np][2], bmr[np][3], sBm + off);
            }
            #pragma unroll
            for (int mt = 0; mt < 2; mt++)
                #pragma unroll
                for (int np = 0; np < 2; np++) {
                    hmma(acc1[mt][2*np],   ah[mt], &bh[np][0]);
                    hmma(acc1[mt][2*np+1], ah[mt], &bh[np][2]);
                }
            #pragma unroll
            for (int mt = 0; mt < 2; mt++)
                #pragma unroll
                for (int np = 0; np < 2; np++) {
                    hmma(acc2[mt][2*np],   am[mt], &bmr[np][0]);
                    hmma(acc2[mt][2*np+1], am[mt], &bmr[np][2]);
                }
        }
        __syncthreads();
    }

    #pragma unroll
    for (int mt = 0; mt < 2; mt++)
        #pragma unroll
        for (int nt = 0; nt < 4; nt++)
            #pragma unroll
            for (int q = 0; q < 4; q++)
                acc1[mt][nt][q] += (acc2[mt][nt][q] - acc1[mt][nt][q]) * SPLIT_INV;

    if (!FUSE_SWIGLU) {
        int r0 = bm + wm + (lane >> 2);
        int cc = bn + wn + (lane & 3) * 2;
        #pragma unroll
        for (int mt = 0; mt < 2; mt++) {
            #pragma unroll
            for (int nt = 0; nt < 4; nt++) {
                float* p0 = C + (size_t)(r0 + mt*16) * N + cc + nt*8;
                float* p1 = p0 + 8 * N;
                *(float2*)p0 = make_float2(acc1[mt][nt][0], acc1[mt][nt][1]);
                *(float2*)p1 = make_float2(acc1[mt][nt][2], acc1[mt][nt][3]);
            }
        }
    } else {
        int r0 = bm + wm + (lane >> 2);
        int uc = ((bn + wn) >> 1) + (lane & 3);
        int UW = N >> 1;
        #pragma unroll
        for (int mt = 0; mt < 2; mt++) {
            #pragma unroll
            for (int nt = 0; nt < 4; nt++) {
                int col = uc + nt*4;
                {
                    float a0 = acc1[mt][nt][0], a1 = acc1[mt][nt][1];
                    float sgl = (a0 / (1.f + expf(-a0))) * a1;
                    __half h, m;
                    split2(sgl, h, m);
                    size_t o = (size_t)(r0 + mt*16) * UW + col;
                    UH[o] = h; UM[o] = m;
                }
                {
                    float a0 = acc1[mt][nt][2], a1 = acc1[mt][nt][3];
                    float sgl = (a0 / (1.f + expf(-a0))) * a1;
                    __half h, m;
                    split2(sgl, h, m);
                    size_t o = (size_t)(r0 + mt*16 + 8) * UW + col;
                    UH[o] = h; UM[o] = m;
                }
            }
        }
    }
}

// ---------------- RoPE + head-major f16 split of q,k,v ----------------
__global__ __launch_bounds__(256) void rope_split_kernel(
    const float* __restrict__ qkv,
    __half* __restrict__ Qh, __half* __restrict__ Qm,
    __half* __restrict__ Kh, __half* __restrict__ Km,
    __half* __restrict__ Vh, __half* __restrict__ Vm)
{
    int idx = blockIdx.x * blockDim.x + threadIdx.x;
    int j   = idx & 31;
    int h   = (idx >> 5) & (NHEAD-1);
    int pos = (idx >> 9) & (SEQ-1);
    int b   = idx >> 20;

    float inv = expf(-(float)j * (9.210340371976184f / 32.f));
    float fr  = (float)pos * inv;
    float s, c;
    sincosf(fr, &s, &c);

    size_t base = (size_t)(b*SEQ + pos) * (3*DIM) + h*DHEAD + j;
    float q1 = qkv[base], q2 = qkv[base+32];
    float k1 = qkv[base+DIM], k2 = qkv[base+DIM+32];
    float v1 = qkv[base+2*DIM], v2 = qkv[base+2*DIM+32];
    float qr1 = q1*c - q2*s, qr2 = q2*c + q1*s;
    float kr1 = k1*c - k2*s, kr2 = k2*c + k1*s;

    size_t o = ((size_t)(b*NHEAD + h)*SEQ + pos) * DHEAD + j;
    __half hh, mm;
    split2(qr1, hh, mm); Qh[o] = hh;    Qm[o] = mm;
    split2(qr2, hh, mm); Qh[o+32] = hh; Qm[o+32] = mm;
    split2(kr1, hh, mm); Kh[o] = hh;    Km[o] = mm;
    split2(kr2, hh, mm); Kh[o+32] = hh; Km[o+32] = mm;
    split2(v1,  hh, mm); Vh[o] = hh;    Vm[o] = mm;
    split2(v2,  hh, mm); Vh[o+32] = hh; Vm[o+32] = mm;
}

// ---------------- tensor-core windowed flash attention ----------------
#define AQT 64
#define AKT 32
#define ATT_SMEM (16384 + 2*16384)

__global__ __launch_bounds__(128) void attn_tc(
    const __half* __restrict__ Qh, const __half* __restrict__ Qm,
    const __half* __restrict__ Kh, const __half* __restrict__ Km,
    const __half* __restrict__ Vh, const __half* __restrict__ Vm,
    __half* __restrict__ cxH, __half* __restrict__ cxM)
{
    extern __shared__ __align__(128) char sm[];
    const uint32_t sb = smem_u32(sm);
    const int tid = threadIdx.x;
    const int w = tid >> 5, lane = tid & 31;
    const int qt0 = blockIdx.x * AQT;
    const int hh = blockIdx.y, b = blockIdx.z;
    const size_t hb = ((size_t)(b*NHEAD + hh)) * SEQ * DHEAD;

    #pragma unroll
    for (int t = 0; t < 4; t++) {
        int i = tid + t*128;
        int r = i >> 3, c = i & 7;
        uint32_t off = swz((uint32_t)(r*128 + c*16));
        size_t g = hb + (size_t)(qt0 + r)*DHEAD + c*8;
        cp16(sb + off,        Qh + g);
        cp16(sb + 8192 + off, Qm + g);
    }
    cp_commit();

    int kstart = qt0 - (WIN-1);
    if (kstart < 0) kstart = 0;
    kstart &= ~(AKT-1);
    const int kend = qt0 + AQT;
    const int niter = (kend - kstart) / AKT;

    auto load_kv = [&](int kt, int s) {
        uint32_t st = sb + 16384 + s*16384;
        #pragma unroll
        for (int t = 0; t < 2; t++) {
            int i = tid + t*128;
            int r = i >> 3, c = i & 7;
            uint32_t off = swz((uint32_t)(r*128 + c*16));
            size_t g = hb + (size_t)(kt + r)*DHEAD + c*8;
            cp16(st + off,         Kh + g);
            cp16(st + 4096 + off,  Km + g);
            cp16(st + 8192 + off,  Vh + g);
            cp16(st + 12288 + off, Vm + g);
        }
        cp_commit();
    };
    load_kv(kstart, 0);

    uint32_t aQh[4][4], aQm[4][4];
    float accC1[8][4], accC2[8][4];
    #pragma unroll
    for (int j = 0; j < 8; j++)
        #pragma unroll
        for (int q = 0; q < 4; q++) { accC1[j][q] = 0.f; accC2[j][q] = 0.f; }
    float m0 = -INFINITY, m1 = -INFINITY, l0 = 0.f, l1 = 0.f;
    const int qrow0 = qt0 + w*16 + (lane >> 2);
    const int qrow1 = qrow0 + 8;
    const int a_row = lane & 15;
    const int kofb  = ((lane >> 4) & 1) * 16;
    const int krow  = (lane & 7) + ((lane >> 3) & 1) * 8;
    const int bcolb = ((lane >> 4) & 1) * 16;
    const int kbrow = (lane & 7) + ((lane >> 4) & 1) * 8;
    const int kbcol = ((lane >> 3) & 1) * 16;

    for (int it = 0; it < niter; it++) {
        int kt = kstart + it * AKT;
        int s = it & 1;
        if (it + 1 < niter) { load_kv(kt + AKT, s ^ 1); cp_wait1(); }
        else cp_wait0();
        __syncthreads();

        if (it == 0) {
            #pragma unroll
            for (int kc = 0; kc < 4; kc++) {
                uint32_t off = swz((uint32_t)((w*16 + a_row)*128 + kc*32 + kofb));
                ldsm4(aQh[kc][0], aQh[kc][1], aQh[kc][2], aQh[kc][3], sb + off);
                ldsm4(aQm[kc][0], aQm[kc][1], aQm[kc][2], aQm[kc][3], sb + 8192 + off);
            }
        }

        uint32_t st  = sb + 16384 + s*16384;
        uint32_t sKh = st, sKm = st + 4096, sVh = st + 8192, sVm = st + 12288;

        float s1[4][4], s2[4][4];
        #pragma unroll
        for (int j = 0; j < 4; j++)
            #pragma unroll
            for (int q = 0; q < 4; q++) { s1[j][q] = 0.f; s2[j][q] = 0.f; }
        #pragma unroll
        for (int kc = 0; kc < 4; kc++) {
            uint32_t off0 = swz((uint32_t)((kbrow)*128      + kc*32 + kbcol));
            uint32_t off1 = swz((uint32_t)((16 + kbrow)*128 + kc*32 + kbcol));
            uint32_t kh0[4], kh1[4], km0[4], km1[4];
            ldsm4(kh0[0], kh0[1], kh0[2], kh0[3], sKh + off0);
            ldsm4(kh1[0], kh1[1], kh1[2], kh1[3], sKh + off1);
            ldsm4(km0[0], km0[1], km0[2], km0[3], sKm + off0);
            ldsm4(km1[0], km1[1], km1[2], km1[3], sKm + off1);
            hmma(s1[0], aQh[kc], &kh0[0]); hmma(s1[1], aQh[kc], &kh0[2]);
            hmma(s1[2], aQh[kc], &kh1[0]); hmma(s1[3], aQh[kc], &kh1[2]);
            hmma(s2[0], aQm[kc], &km0[0]); hmma(s2[1], aQm[kc], &km0[2]);
            hmma(s2[2], aQm[kc], &km1[0]); hmma(s2[3], aQm[kc], &km1[2]);
        }

        float pv0[8], pv1[8];
        float tmax0 = -INFINITY, tmax1 = -INFINITY;
        #pragma unroll
        for (int j = 0; j < 4; j++) {
            int kc0 = kt + j*8 + 2*(lane & 3);
            #pragma unroll
            for (int e = 0; e < 2; e++) {
                int kk = kc0 + e;
                float v = s1[j][e] + (s2[j][e] - s1[j][e]) * SPLIT_INV;
                v *= 0.125f;
                v = (kk <= qrow0 && kk >= qrow0 - (WIN-1)) ? v : -INFINITY;
                pv0[j*2+e] = v; tmax0 = fmaxf(tmax0, v);
                float u = s1[j][2+e] + (s2[j][2+e] - s1[j][2+e]) * SPLIT_INV;
                u *= 0.125f;
                u = (kk <= qrow1 && kk >= qrow1 - (WIN-1)) ? u : -INFINITY;
                pv1[j*2+e] = u; tmax1 = fmaxf(tmax1, u);
            }
        }
        tmax0 = fmaxf(tmax0, __shfl_xor_sync(~0u, tmax0, 1));
        tmax0 = fmaxf(tmax0, __shfl_xor_sync(~0u, tmax0, 2));
        tmax1 = fmaxf(tmax1, __shfl_xor_sync(~0u, tmax1, 1));
        tmax1 = fmaxf(tmax1, __shfl_xor_sync(~0u, tmax1, 2));
        float mn0 = fmaxf(m0, tmax0), mn1 = fmaxf(m1, tmax1);
        bool dead0 = (mn0 == -INFINITY), dead1 = (mn1 == -INFINITY);
        float corr0 = dead0 ? 1.f : __expf(m0 - mn0);
        float corr1 = dead1 ? 1.f : __expf(m1 - mn1);
        float sum0 = 0.f, sum1 = 0.f;
        #pragma unroll
        for (int i = 0; i < 8; i++) {
            float p0 = dead0 ? 0.f : __expf(pv0[i] - mn0);
            float p1 = dead1 ? 0.f : __expf(pv1[i] - mn1);
            pv0[i] = p0; pv1[i] = p1;
            sum0 += p0; sum1 += p1;
        }
        sum0 += __shfl_xor_sync(~0u, sum0, 1);
        sum0 += __shfl_xor_sync(~0u, sum0, 2);
        sum1 += __shfl_xor_sync(~0u, sum1, 1);
        sum1 += __shfl_xor_sync(~0u, sum1, 2);
        l0 = l0 * corr0 + sum0; m0 = mn0;
        l1 = l1 * corr1 + sum1; m1 = mn1;
        #pragma unroll
        for (int j = 0; j < 8; j++) {
            accC1[j][0] *= corr0; accC1[j][1] *= corr0;
            accC1[j][2] *= corr1; accC1[j][3] *= corr1;
            accC2[j][0] *= corr0; accC2[j][1] *= corr0;
            accC2[j][2] *= corr1; accC2[j][3] *= corr1;
        }

        #pragma unroll
        for (int kc2 = 0; kc2 < 2; kc2++) {
            uint32_t aPh[4], aPm[4];
            {
                __half h0,mh0,h1,mh1;
                split2(pv0[kc2*4+0], h0, mh0); split2(pv0[kc2*4+1], h1, mh1);
                aPh[0] = pack2(h0, h1); aPm[0] = pack2(mh0, mh1);
                split2(pv1[kc2*4+0], h0, mh0); split2(pv1[kc2*4+1], h1, mh1);
                aPh[1] = pack2(h0, h1); aPm[1] = pack2(mh0, mh1);
                split2(pv0[kc2*4+2], h0, mh0); split2(pv0[kc2*4+3], h1, mh1);
                aPh[2] = pack2(h0, h1); aPm[2] = pack2(mh0, mh1);
                split2(pv1[kc2*4+2], h0, mh0); split2(pv1[kc2*4+3], h1, mh1);
                aPh[3] = pack2(h0, h1); aPm[3] = pack2(mh0, mh1);
            }
            int vrow = kc2*16 + krow;
            #pragma unroll
            for (int dc = 0; dc < 4; dc++) {
                uint32_t off = swz((uint32_t)(vrow*128 + dc*32 + bcolb));
                uint32_t vh[4], vm[4];
                ldsm4t(vh[0], vh[1], vh[2], vh[3], sVh + off);
                ldsm4t(vm[0], vm[1], vm[2], vm[3], sVm + off);
                hmma(accC1[dc*2+0], aPh, &vh[0]); hmma(accC1[dc*2+1], aPh, &vh[2]);
                hmma(accC2[dc*2+0], aPm, &vm[0]); hmma(accC2[dc*2+1], aPm, &vm[2]);
            }
        }
        __syncthreads();
    }

    float invl0 = 1.f / l0, invl1 = 1.f / l1;
    #pragma unroll
    for (int j = 0; j < 8; j++) {
        float c0 = accC1[j][0] + (accC2[j][0] - accC1[j][0]) * SPLIT_INV;
        float c1 = accC1[j][1] + (accC2[j][1] - accC1[j][1]) * SPLIT_INV;
        float c2 = accC1[j][2] + (accC2[j][2] - accC1[j][2]) * SPLIT_INV;
        float c3 = accC1[j][3] + (accC2[j][3] - accC1[j][3]) * SPLIT_INV;
        c0 *= invl0; c1 *= invl0; c2 *= invl1; c3 *= invl1;
        int dh = hh*DHEAD + j*8 + 2*(lane & 3);
        size_t a0 = (size_t)(b*SEQ + qrow0)*DIM + dh;
        size_t a1 = (size_t)(b*SEQ + qrow1)*DIM + dh;
        __half h0,mm0,h1,mm1;
        split2(c0, h0, mm0); split2(c1, h1, mm1);
        *(__half2*)(cxH + a0) = __halves2half2(h0, h1);
        *(__half2*)(cxM + a0) = __halves2half2(mm0, mm1);
        split2(c2, h0, mm0); split2(c3, h1, mm1);
        *(__half2*)(cxH + a1) = __halves2half2(h0, h1);
        *(__half2*)(cxM + a1) = __halves2half2(mm0, mm1);
    }
}

// ---------------- host orchestration ----------------
extern "C" void kernel_launch(void* const* d_in, const int* in_sizes, int n_in,
                              void* d_out, int out_size)
{
    const float* x_in = (const float*)d_in[0];
    const float* Wqkv = (const float*)d_in[2];
    const float* Wout = (const float*)d_in[3];
    const float* fc1  = (const float*)d_in[4];
    const float* fc2  = (const float*)d_in[5];
    const float* n1w  = (const float*)d_in[6];
    const float* n2w  = (const float*)d_in[7];
    const float* fnw  = (const float*)d_in[8];
    float* out = (float*)d_out;

    float *res, *qkv, *aab, *xx;
    __half *hnH, *hnM, *cxH, *cxM, *uH, *uM;
    __half *qkvH, *qkvM, *woH, *woM, *f1H, *f1M, *f2H, *f2M;
    __half *Qh, *Qm, *Kh, *Km, *Vh, *Vm;

    cudaGetSymbolAddress((void**)&res, g_res);
    cudaGetSymbolAddress((void**)&qkv, g_qkv);
    cudaGetSymbolAddress((void**)&aab, g_a);
    cudaGetSymbolAddress((void**)&xx,  g_x);
    cudaGetSymbolAddress((void**)&hnH, g_hnH);
    cudaGetSymbolAddress((void**)&hnM, g_hnM);
    cudaGetSymbolAddress((void**)&cxH, g_cxH);
    cudaGetSymbolAddress((void**)&cxM, g_cxM);
    cudaGetSymbolAddress((void**)&uH,  g_uH);
    cudaGetSymbolAddress((void**)&uM,  g_uM);
    cudaGetSymbolAddress((void**)&qkvH, g_qkvH);
    cudaGetSymbolAddress((void**)&qkvM, g_qkvM);
    cudaGetSymbolAddress((void**)&woH,  g_woH);
    cudaGetSymbolAddress((void**)&woM,  g_woM);
    cudaGetSymbolAddress((void**)&f1H,  g_f1H);
    cudaGetSymbolAddress((void**)&f1M,  g_f1M);
    cudaGetSymbolAddress((void**)&f2H,  g_f2H);
    cudaGetSymbolAddress((void**)&f2M,  g_f2M);
    cudaGetSymbolAddress((void**)&Qh, g_Qh);
    cudaGetSymbolAddress((void**)&Qm, g_Qm);
    cudaGetSymbolAddress((void**)&Kh, g_Kh);
    cudaGetSymbolAddress((void**)&Km, g_Km);
    cudaGetSymbolAddress((void**)&Vh, g_Vh);
    cudaGetSymbolAddress((void**)&Vm, g_Vm);

    cudaFuncSetAttribute(gemm_2t<false>, cudaFuncAttributeMaxDynamicSharedMemorySize, GEMM_SMEM);
    cudaFuncSetAttribute(gemm_2t<true>,  cudaFuncAttributeMaxDynamicSharedMemorySize, GEMM_SMEM);
    cudaFuncSetAttribute(attn_tc, cudaFuncAttributeMaxDynamicSharedMemorySize, ATT_SMEM);

    // launches 0..2, QKV GEMM at index 3 (ncu capture target)
    add_rmsnorm_split<<<MROWS, 256>>>(x_in, (const float*)nullptr,
                                      res, hnH, hnM, n1w);
    {
        int n4 = NLAYER*3*DIM*DIM/4;
        split_kernel<<<(n4+255)/256, 256>>>((const float4*)Wqkv, qkvH, qkvM, n4);
        n4 = NLAYER*DIM*DIM/4;
        split_kernel<<<(n4+255)/256, 256>>>((const float4*)Wout, woH, woM, n4);
    }

    for (int l = 0; l < NLAYER; l++) {
        if (l > 0)
            add_rmsnorm_split<<<MROWS, 256>>>(xx, res, res, hnH, hnM,
                                              n1w + (size_t)l*DIM);

        gemm_2t<false><<<dim3(3*DIM/BN, MROWS/BM), GTHREADS, GEMM_SMEM>>>(
            hnH, hnM,
            qkvH + (size_t)l*3*DIM*DIM, qkvM + (size_t)l*3*DIM*DIM,
            qkv, nullptr, nullptr, 3*DIM, DIM);

        if (l == 0) {
            int n4 = NLAYER*2*DFFN*DIM/4;
            split_fc1_kernel<<<(n4+255)/256, 256>>>((const float4*)fc1, f1H, f1M, n4);
            n4 = NLAYER*DIM*DFFN/4;
            split_kernel<<<(n4+255)/256, 256>>>((const float4*)fc2, f2H, f2M, n4);
        }

        rope_split_kernel<<<(BATCH*SEQ*NHEAD*32)/256, 256>>>(
            qkv, Qh, Qm, Kh, Km, Vh, Vm);

        attn_tc<<<dim3(SEQ/AQT, NHEAD, BATCH), 128, ATT_SMEM>>>(
            Qh, Qm, Kh, Km, Vh, Vm, cxH, cxM);

        gemm_2t<false><<<dim3(DIM/BN, MROWS/BM), GTHREADS, GEMM_SMEM>>>(
            cxH, cxM,
            woH + (size_t)l*DIM*DIM, woM + (size_t)l*DIM*DIM,
            aab, nullptr, nullptr, DIM, DIM);

        add_rmsnorm_split<<<MROWS, 256>>>(aab, res, res, hnH, hnM,
                                          n2w + (size_t)l*DIM);

        gemm_2t<true><<<dim3(2*DFFN/BN, MROWS/BM), GTHREADS, GEMM_SMEM>>>(
            hnH, hnM,
            f1H + (size_t)l*2*DFFN*DIM, f1M + (size_t)l*2*DFFN*DIM,
            nullptr, uH, uM, 2*DFFN, DIM);

        gemm_2t<false><<<dim3(DIM/BN, MROWS/BM), GTHREADS, GEMM_SMEM>>>(
            uH, uM,
            f2H + (size_t)l*DIM*DFFN, f2M + (size_t)l*DIM*DFFN,
            xx, nullptr, nullptr, DIM, DFFN);
    }

    add_rmsnorm_f32<<<MROWS, 256>>>(xx, res, out, fnw);
}